// round 5
// baseline (speedup 1.0000x reference)
#include <cuda_runtime.h>
#include <cuda_fp16.h>
#include <cstdint>

// ============================================================================
// GLinear on plain sm_103 target (no tcgen05 available in this toolchain):
//   pack:   x[P,C,16] f32 -> 16 fp16 planes g_xh[d][P*C]   (coalesced transpose)
//   wsplit: W f32 -> Whi, Wlo fp16                          (error ~eps^2 on W)
//   gemm:   per CTA (64p x 64o x 4d), cp.async + ldmatrix + mma.sync m16n8k16,
//           2 terms (Whi*x + Wlo*x), fp32 accum, fused residual + float4 store.
// ============================================================================

static constexpr int PC = 8192 * 256;            // 2097152
__device__ __half g_xh[16][PC];                  // 64 MB packed x (fp16)
__device__ __half g_Whi[3][65536];
__device__ __half g_Wlo[3][65536];

// ---------------------------------------------------------------------------
__device__ __forceinline__ uint32_t smem_u32(const void* p) {
    uint32_t a;
    asm("{ .reg .u64 t; cvta.to.shared.u64 t, %1; cvt.u32.u64 %0, t; }" : "=r"(a) : "l"(p));
    return a;
}
__device__ __forceinline__ uint32_t sw128(uint32_t o) { return o ^ ((o >> 3) & 0x70); }

#define CP16(dst, src) \
    asm volatile("cp.async.cg.shared.global [%0], [%1], 16;" :: "r"(dst), "l"(src))
#define CP_COMMIT() asm volatile("cp.async.commit_group;" ::: "memory")
#define CP_WAIT1()  asm volatile("cp.async.wait_group 1;" ::: "memory")
#define CP_WAIT0()  asm volatile("cp.async.wait_group 0;" ::: "memory")

__device__ __forceinline__ void ldsm4(uint32_t (&r)[4], uint32_t addr) {
    asm volatile("ldmatrix.sync.aligned.m8n8.x4.shared.b16 {%0,%1,%2,%3}, [%4];"
                 : "=r"(r[0]), "=r"(r[1]), "=r"(r[2]), "=r"(r[3]) : "r"(addr));
}
__device__ __forceinline__ void mma16816(float (&c)[4], const uint32_t (&a)[4],
                                         uint32_t b0, uint32_t b1) {
    asm volatile(
        "mma.sync.aligned.m16n8k16.row.col.f32.f16.f16.f32 "
        "{%0,%1,%2,%3}, {%4,%5,%6,%7}, {%8,%9}, {%0,%1,%2,%3};"
        : "+f"(c[0]), "+f"(c[1]), "+f"(c[2]), "+f"(c[3])
        : "r"(a[0]), "r"(a[1]), "r"(a[2]), "r"(a[3]), "r"(b0), "r"(b1));
}

// ---------------------------------------------------------------------------
// pack: x[n][16] f32 (n = p*256+i) -> g_xh[d][n] fp16. CTA tile: 512 n-rows.
// ---------------------------------------------------------------------------
__global__ void __launch_bounds__(256) pack_kernel(const float* __restrict__ x) {
    __shared__ __half sh[16][528];                       // 528*2B = 1056 = 66*16
    const int n0 = blockIdx.x * 512;
    const int tid = threadIdx.x;
#pragma unroll
    for (int t = 0; t < 8; t++) {
        int id = tid + t * 256;                          // 0..2047 float4s
        int n = id >> 2, dq = id & 3;
        float4 v = reinterpret_cast<const float4*>(x)[(size_t)(n0 + n) * 4 + dq];
        sh[dq * 4 + 0][n] = __float2half_rn(v.x);
        sh[dq * 4 + 1][n] = __float2half_rn(v.y);
        sh[dq * 4 + 2][n] = __float2half_rn(v.z);
        sh[dq * 4 + 3][n] = __float2half_rn(v.w);
    }
    __syncthreads();
#pragma unroll
    for (int j = 0; j < 4; j++) {
        int u = j * 256 + tid;                           // 0..1023
        int d = u >> 6, c = u & 63;
        uint4 v = *reinterpret_cast<const uint4*>(&sh[d][c * 8]);
        *reinterpret_cast<uint4*>(&g_xh[d][n0 + c * 8]) = v;
    }
}

// ---------------------------------------------------------------------------
__global__ void __launch_bounds__(256) wsplit_kernel(const float* __restrict__ W00,
                                                     const float* __restrict__ W10,
                                                     const float* __restrict__ W11) {
    int i = blockIdx.x * 256 + threadIdx.x;
    if (i >= 3 * 65536) return;
    int w = i >> 16, j = i & 65535;
    const float* src = (w == 0) ? W00 : ((w == 1) ? W10 : W11);
    float v = src[j];
    __half h = __float2half_rn(v);
    g_Whi[w][j] = h;
    g_Wlo[w][j] = __float2half_rn(v - __half2float(h));
}

// ---------------------------------------------------------------------------
// GEMM: grid 2048 = 128 pt x 4 dg x 4 ot ; bid = pt*16 + dg*4 + ot
// CTA: 64p x 64o x 4d, K=256 in 4 chunks of 64, cp.async double-buffered.
// smem stage: A[4d][64p][64k] fp16 + B[2slot][2split][64o][64k] fp16 = 64KB.
// ---------------------------------------------------------------------------
static constexpr int A_TILE = 64 * 128;   // bytes
static constexpr int B_TILE = 64 * 128;
static constexpr int STAGE  = 4 * A_TILE + 4 * B_TILE;  // 65536
static constexpr int SMEMSZ = 2 * STAGE;                // 131072

__global__ void __launch_bounds__(256, 1)
gemm_kernel(const float* __restrict__ x, float* __restrict__ out) {
    extern __shared__ char smem[];
    const uint32_t sb = smem_u32(smem);
    const int tid = threadIdx.x;
    const int wid = tid >> 5, lane = tid & 31;
    const int wp = wid >> 2, wo = wid & 3;       // 2 p-warps x 4 o-warps
    const int g = lane >> 2, c2 = lane & 3;

    const int bid = blockIdx.x;
    const int pt = bid >> 4, dg = (bid >> 2) & 3, ot = bid & 3;
    const int p0 = pt * 64, o0 = ot * 64;

    // W mapping for this d-group (<=2 distinct W -> 2 slots)
    int w_of[4];
#pragma unroll
    for (int dd = 0; dd < 4; dd++) {
        int d = dg * 4 + dd;
        w_of[dd] = (d == 0) ? 0 : ((d < 7) ? 1 : 2);
    }
    int w0 = w_of[0], w1 = w0;
#pragma unroll
    for (int dd = 1; dd < 4; dd++)
        if (w_of[dd] != w0) w1 = w_of[dd];
    int slot_of[4];
#pragma unroll
    for (int dd = 0; dd < 4; dd++) slot_of[dd] = (w_of[dd] == w0) ? 0 : 1;

    // per-thread cp.async assignment: one 128B row of one subtile per thread
    const int arow = tid & 63;
    const int asub = tid >> 6;                    // A: d ; B: slot*2+split
    const __half* wsrc = (asub & 1) ? g_Wlo[(asub >> 1) ? w1 : w0]
                                    : g_Whi[(asub >> 1) ? w1 : w0];
    const __half* aSrc = &g_xh[dg * 4 + asub][(size_t)(p0 + arow) * 256];
    const __half* bSrc = wsrc + (size_t)(o0 + arow) * 256;

    float acc[4][2][2][4];
#pragma unroll
    for (int d = 0; d < 4; d++)
#pragma unroll
        for (int m = 0; m < 2; m++)
#pragma unroll
            for (int n = 0; n < 2; n++)
#pragma unroll
                for (int e = 0; e < 4; e++) acc[d][m][n][e] = 0.f;

    // residual gmem offsets (also epilogue store offsets): it = m*8 + n2*4 + e
    size_t gofs[16];
#pragma unroll
    for (int it = 0; it < 16; it++) {
        int m = it >> 3, n2 = (it >> 2) & 1, e = it & 3;
        int p = p0 + wp * 32 + m * 16 + g + (e >> 1) * 8;
        int o = o0 + wo * 16 + n2 * 8 + c2 * 2 + (e & 1);
        gofs[it] = (size_t)p * 4096 + (size_t)o * 16 + dg * 4;
    }

    auto issue = [&](int c, int b) {
        uint32_t s0 = sb + b * STAGE;
        const __half* as = aSrc + c * 64;
        const __half* bs = bSrc + c * 64;
#pragma unroll
        for (int q = 0; q < 8; q++) {
            uint32_t off = sw128((uint32_t)(arow * 128 + q * 16));
            CP16(s0 + asub * A_TILE + off, as + q * 8);
            CP16(s0 + 4 * A_TILE + asub * B_TILE + off, bs + q * 8);
        }
        CP_COMMIT();
    };

    auto compute = [&](int b) {
        uint32_t s0 = sb + b * STAGE;
        const uint32_t rowB = (uint32_t)(wo * 16 + (lane & 15)) * 128;
        const uint32_t rowA0 = (uint32_t)(wp * 32 + (lane & 15)) * 128;
#pragma unroll
        for (int s = 0; s < 4; s++) {
            const uint32_t qb = (uint32_t)(s * 2 + (lane >> 4)) * 16;
            uint32_t bf[4][4];
#pragma unroll
            for (int u = 0; u < 4; u++)
                ldsm4(bf[u], s0 + 4 * A_TILE + u * B_TILE + sw128(rowB + qb));
#pragma unroll
            for (int d = 0; d < 4; d++) {
                uint32_t a0[4], a1[4];
                ldsm4(a0, s0 + d * A_TILE + sw128(rowA0 + qb));
                ldsm4(a1, s0 + d * A_TILE + sw128(rowA0 + 16 * 128 + qb));
                const int sl = slot_of[d];
#pragma unroll
                for (int t = 0; t < 2; t++) {
                    const uint32_t* B = bf[sl * 2 + t];
                    mma16816(acc[d][0][0], a0, B[0], B[2]);
                    mma16816(acc[d][0][1], a0, B[1], B[3]);
                    mma16816(acc[d][1][0], a1, B[0], B[2]);
                    mma16816(acc[d][1][1], a1, B[1], B[3]);
                }
            }
        }
    };

    issue(0, 0);
#pragma unroll
    for (int c = 0; c < 4; c++) {
        if (c + 1 < 4) issue(c + 1, (c + 1) & 1);
        if (c == 3) {
            // prefetch residual float4s into buf0 (free: compute(2) used it, done)
#pragma unroll
            for (int it = 0; it < 16; it++)
                CP16(sb + tid * 256 + it * 16, x + gofs[it]);
            CP_COMMIT();
        }
        if (c < 3) { CP_WAIT1(); } else { CP_WAIT1(); }
        __syncthreads();
        compute(c & 1);
        __syncthreads();
    }
    CP_WAIT0();   // residual prefetch done (per-thread data, no barrier needed)

    // epilogue: acc + residual -> float4 stores (4 d's contiguous = 16B)
#pragma unroll
    for (int it = 0; it < 16; it++) {
        int m = it >> 3, n2 = (it >> 2) & 1, e = it & 3;
        float4 r = *reinterpret_cast<const float4*>(smem + tid * 256 + it * 16);
        float4 v;
        v.x = acc[0][m][n2][e] + r.x;
        v.y = acc[1][m][n2][e] + r.y;
        v.z = acc[2][m][n2][e] + r.z;
        v.w = acc[3][m][n2][e] + r.w;
        *reinterpret_cast<float4*>(out + gofs[it]) = v;
    }
}

// ---------------------------------------------------------------------------
extern "C" void kernel_launch(void* const* d_in, const int* in_sizes, int n_in,
                              void* d_out, int out_size) {
    const float* x   = (const float*)d_in[0];
    const float* W00 = (const float*)d_in[1];
    const float* W10 = (const float*)d_in[2];
    const float* W11 = (const float*)d_in[3];
    float* out = (float*)d_out;

    pack_kernel<<<PC / 512, 256>>>(x);
    wsplit_kernel<<<768, 256>>>(W00, W10, W11);

    cudaFuncSetAttribute(gemm_kernel,
                         cudaFuncAttributeMaxDynamicSharedMemorySize, SMEMSZ);
    gemm_kernel<<<2048, 256, SMEMSZ>>>(x, out);
}

// round 6
// speedup vs baseline: 1.2828x; 1.2828x over previous
#include <cuda_runtime.h>
#include <cuda_fp16.h>
#include <cstdint>

// ============================================================================
// GLinear on plain sm_103 target (tcgen05 unavailable in this toolchain):
//   pack:   x[P,C,16] f32 -> 16 fp16 planes g_xh[d][P*C]  (coalesced transpose)
//   wsplit: W f32 -> fp16 (single term; rel_err budget allows it)
//   gemm:   CTA = 64p x 64o x 4d, cp.async double-buffer + ldmatrix +
//           mma.sync.m16n8k16 fp16->fp32, 2 CTAs/SM, fused residual + f4 store.
// ============================================================================

static constexpr int PC = 8192 * 256;            // 2097152
__device__ __half g_xh[16][PC];                  // 64 MB packed x (fp16)
__device__ __half g_Wh[3][65536];

// ---------------------------------------------------------------------------
__device__ __forceinline__ uint32_t smem_u32(const void* p) {
    uint32_t a;
    asm("{ .reg .u64 t; cvta.to.shared.u64 t, %1; cvt.u32.u64 %0, t; }" : "=r"(a) : "l"(p));
    return a;
}
__device__ __forceinline__ uint32_t sw128(uint32_t o) { return o ^ ((o >> 3) & 0x70); }

#define CP16(dst, src) \
    asm volatile("cp.async.cg.shared.global [%0], [%1], 16;" :: "r"(dst), "l"(src))
#define CP_COMMIT() asm volatile("cp.async.commit_group;" ::: "memory")
#define CP_WAIT1()  asm volatile("cp.async.wait_group 1;" ::: "memory")
#define CP_WAIT0()  asm volatile("cp.async.wait_group 0;" ::: "memory")

__device__ __forceinline__ void ldsm4(uint32_t (&r)[4], uint32_t addr) {
    asm volatile("ldmatrix.sync.aligned.m8n8.x4.shared.b16 {%0,%1,%2,%3}, [%4];"
                 : "=r"(r[0]), "=r"(r[1]), "=r"(r[2]), "=r"(r[3]) : "r"(addr));
}
__device__ __forceinline__ void mma16816(float (&c)[4], const uint32_t (&a)[4],
                                         uint32_t b0, uint32_t b1) {
    asm volatile(
        "mma.sync.aligned.m16n8k16.row.col.f32.f16.f16.f32 "
        "{%0,%1,%2,%3}, {%4,%5,%6,%7}, {%8,%9}, {%0,%1,%2,%3};"
        : "+f"(c[0]), "+f"(c[1]), "+f"(c[2]), "+f"(c[3])
        : "r"(a[0]), "r"(a[1]), "r"(a[2]), "r"(a[3]), "r"(b0), "r"(b1));
}

// ---------------------------------------------------------------------------
// pack: x[n][16] f32 (n = p*256+i) -> g_xh[d][n] fp16. CTA tile: 512 n-rows.
// ---------------------------------------------------------------------------
__global__ void __launch_bounds__(256) pack_kernel(const float* __restrict__ x) {
    __shared__ __half sh[16][528];
    const int n0 = blockIdx.x * 512;
    const int tid = threadIdx.x;
#pragma unroll
    for (int t = 0; t < 8; t++) {
        int id = tid + t * 256;
        int n = id >> 2, dq = id & 3;
        float4 v = reinterpret_cast<const float4*>(x)[(size_t)(n0 + n) * 4 + dq];
        sh[dq * 4 + 0][n] = __float2half_rn(v.x);
        sh[dq * 4 + 1][n] = __float2half_rn(v.y);
        sh[dq * 4 + 2][n] = __float2half_rn(v.z);
        sh[dq * 4 + 3][n] = __float2half_rn(v.w);
    }
    __syncthreads();
#pragma unroll
    for (int j = 0; j < 4; j++) {
        int u = j * 256 + tid;
        int d = u >> 6, c = u & 63;
        uint4 v = *reinterpret_cast<const uint4*>(&sh[d][c * 8]);
        *reinterpret_cast<uint4*>(&g_xh[d][n0 + c * 8]) = v;
    }
}

// ---------------------------------------------------------------------------
__global__ void __launch_bounds__(256) wsplit_kernel(const float* __restrict__ W00,
                                                     const float* __restrict__ W10,
                                                     const float* __restrict__ W11) {
    int i = blockIdx.x * 256 + threadIdx.x;
    if (i >= 3 * 65536) return;
    int w = i >> 16, j = i & 65535;
    const float* src = (w == 0) ? W00 : ((w == 1) ? W10 : W11);
    g_Wh[w][j] = __float2half_rn(src[j]);
}

// ---------------------------------------------------------------------------
// GEMM: grid 2048 = 128 pt x 4 dg x 4 ot ; bid = pt*16 + dg*4 + ot
// CTA: 64p x 64o x 4d, K=256 in 4 chunks of 64, cp.async double-buffered.
// stage: A[4d][64p][64k] + B[2slot][64o][64k] fp16 = 48 KB; x2 = 96 KB.
// ---------------------------------------------------------------------------
static constexpr int A_TILE = 64 * 128;                 // 8 KB
static constexpr int B_TILE = 64 * 128;                 // 8 KB
static constexpr int STAGE  = 4 * A_TILE + 2 * B_TILE;  // 49152
static constexpr int SMEMSZ = 2 * STAGE;                // 98304 -> 2 CTAs/SM

__global__ void __launch_bounds__(256, 2)
gemm_kernel(const float* __restrict__ x, float* __restrict__ out) {
    extern __shared__ char smem[];
    const uint32_t sb = smem_u32(smem);
    const int tid = threadIdx.x;
    const int wid = tid >> 5, lane = tid & 31;
    const int wp = wid >> 2, wo = wid & 3;       // 2 p-warps x 4 o-warps
    const int g = lane >> 2, c2 = lane & 3;

    const int bid = blockIdx.x;
    const int pt = bid >> 4, dg = (bid >> 2) & 3, ot = bid & 3;
    const int p0 = pt * 64, o0 = ot * 64;

    // W mapping for this d-group (<=2 distinct W -> 2 slots)
    int w_of[4];
#pragma unroll
    for (int dd = 0; dd < 4; dd++) {
        int d = dg * 4 + dd;
        w_of[dd] = (d == 0) ? 0 : ((d < 7) ? 1 : 2);
    }
    int w0 = w_of[0], w1 = w0;
#pragma unroll
    for (int dd = 1; dd < 4; dd++)
        if (w_of[dd] != w0) w1 = w_of[dd];
    int slot_of[4];
#pragma unroll
    for (int dd = 0; dd < 4; dd++) slot_of[dd] = (w_of[dd] == w0) ? 0 : 1;

    // cp.async assignment:
    //   all 256 threads: A row (d = tid>>6, row = tid&63)        8 x CP16
    //   threads < 128:   B row (slot = tid>>6, row = tid&63)     8 x CP16
    const int arow = tid & 63;
    const int asub = tid >> 6;
    const __half* aSrc = &g_xh[dg * 4 + asub][(size_t)(p0 + arow) * 256];
    const __half* bSrc = g_Wh[(tid >> 6) ? w1 : w0] + (size_t)(o0 + arow) * 256;
    const bool doB = tid < 128;

    float acc[4][2][2][4];
#pragma unroll
    for (int d = 0; d < 4; d++)
#pragma unroll
        for (int m = 0; m < 2; m++)
#pragma unroll
            for (int n = 0; n < 2; n++)
#pragma unroll
                for (int e = 0; e < 4; e++) acc[d][m][n][e] = 0.f;

    auto issue = [&](int c, int b) {
        uint32_t s0 = sb + b * STAGE;
        const __half* as = aSrc + c * 64;
#pragma unroll
        for (int q = 0; q < 8; q++) {
            uint32_t off = sw128((uint32_t)(arow * 128 + q * 16));
            CP16(s0 + asub * A_TILE + off, as + q * 8);
        }
        if (doB) {
            const __half* bs = bSrc + c * 64;
            uint32_t bt = s0 + 4 * A_TILE + (tid >> 6) * B_TILE;
#pragma unroll
            for (int q = 0; q < 8; q++) {
                uint32_t off = sw128((uint32_t)(arow * 128 + q * 16));
                CP16(bt + off, bs + q * 8);
            }
        }
        CP_COMMIT();
    };

    auto compute = [&](int b) {
        uint32_t s0 = sb + b * STAGE;
        const uint32_t rowB = (uint32_t)(wo * 16 + (lane & 15)) * 128;
        const uint32_t rowA0 = (uint32_t)(wp * 32 + (lane & 15)) * 128;
#pragma unroll
        for (int s = 0; s < 4; s++) {
            const uint32_t qb = (uint32_t)(s * 2 + (lane >> 4)) * 16;
            uint32_t bf[2][4];
#pragma unroll
            for (int u = 0; u < 2; u++)
                ldsm4(bf[u], s0 + 4 * A_TILE + u * B_TILE + sw128(rowB + qb));
#pragma unroll
            for (int d = 0; d < 4; d++) {
                uint32_t a0[4], a1[4];
                ldsm4(a0, s0 + d * A_TILE + sw128(rowA0 + qb));
                ldsm4(a1, s0 + d * A_TILE + sw128(rowA0 + 16 * 128 + qb));
                const uint32_t* B = bf[slot_of[d]];
                mma16816(acc[d][0][0], a0, B[0], B[2]);
                mma16816(acc[d][0][1], a0, B[1], B[3]);
                mma16816(acc[d][1][0], a1, B[0], B[2]);
                mma16816(acc[d][1][1], a1, B[1], B[3]);
            }
        }
    };

    issue(0, 0);
#pragma unroll
    for (int c = 0; c < 4; c++) {
        if (c + 1 < 4) { issue(c + 1, (c + 1) & 1); CP_WAIT1(); }
        else           { CP_WAIT0(); }
        __syncthreads();
        compute(c & 1);
        __syncthreads();
    }

    // epilogue: acc + residual -> float4 stores (4 d's contiguous = 16B)
#pragma unroll
    for (int m = 0; m < 2; m++)
#pragma unroll
        for (int n2 = 0; n2 < 2; n2++)
#pragma unroll
            for (int e = 0; e < 4; e++) {
                int p = p0 + wp * 32 + m * 16 + g + (e >> 1) * 8;
                int o = o0 + wo * 16 + n2 * 8 + c2 * 2 + (e & 1);
                size_t go = (size_t)p * 4096 + (size_t)o * 16 + dg * 4;
                float4 r = *reinterpret_cast<const float4*>(x + go);
                float4 v;
                v.x = acc[0][m][n2][e] + r.x;
                v.y = acc[1][m][n2][e] + r.y;
                v.z = acc[2][m][n2][e] + r.z;
                v.w = acc[3][m][n2][e] + r.w;
                *reinterpret_cast<float4*>(out + go) = v;
            }
}

// ---------------------------------------------------------------------------
extern "C" void kernel_launch(void* const* d_in, const int* in_sizes, int n_in,
                              void* d_out, int out_size) {
    const float* x   = (const float*)d_in[0];
    const float* W00 = (const float*)d_in[1];
    const float* W10 = (const float*)d_in[2];
    const float* W11 = (const float*)d_in[3];
    float* out = (float*)d_out;

    pack_kernel<<<PC / 512, 256>>>(x);
    wsplit_kernel<<<768, 256>>>(W00, W10, W11);

    cudaFuncSetAttribute(gemm_kernel,
                         cudaFuncAttributeMaxDynamicSharedMemorySize, SMEMSZ);
    gemm_kernel<<<2048, 256, SMEMSZ>>>(x, out);
}